// round 9
// baseline (speedup 1.0000x reference)
#include <cuda_runtime.h>
#include <cuda_bf16.h>
#include <cstdint>

#define NUM_CAMS   500
#define NUM_POINTS 100000
#define MAX_E      250000
#define D          256

// ---------------- scratch (device globals; no allocations allowed) ----------
__device__ float d_cam_agg[NUM_CAMS * D];
__device__ float d_point_agg[NUM_POINTS * D];
__device__ float d_g_cam[NUM_CAMS * D];
__device__ float d_g_point[NUM_POINTS * D];
__device__ float d_s_cam[NUM_CAMS];
__device__ float d_s_point[NUM_POINTS];
// fused weight matrices, bf16 hi/lo split, [n][k] layout (k contiguous)
__device__ __nv_bfloat16 d_Bch[D * D];
__device__ __nv_bfloat16 d_Bcl[D * D];
__device__ __nv_bfloat16 d_Bph[D * D];
__device__ __nv_bfloat16 d_Bpl[D * D];
__device__ float d_vc[D];
__device__ float d_vp[D];
__device__ float d_score[MAX_E];
__device__ float d_expv[MAX_E];
__device__ unsigned int d_gmax_u;
__device__ float d_gsum;

// ---------------- helpers ----------------------------------------------------
__device__ __forceinline__ unsigned int fenc(float f) {
    unsigned int u = __float_as_uint(f);
    return (u & 0x80000000u) ? ~u : (u | 0x80000000u);
}
__device__ __forceinline__ float fdec(unsigned int x) {
    return (x & 0x80000000u) ? __uint_as_float(x & 0x7fffffffu)
                             : __uint_as_float(~x);
}

__device__ __forceinline__ void red_add_v4(float* p, float4 v) {
    asm volatile("red.global.add.v4.f32 [%0], {%1, %2, %3, %4};"
                 :: "l"(p), "f"(v.x), "f"(v.y), "f"(v.z), "f"(v.w)
                 : "memory");
}

__global__ void init_scalars_kernel() {
    d_gmax_u = 0u;     // encodes -inf
    d_gsum = 0.0f;
}

// ---------------- fold weights: M[n][k] = sum_j Wf[n][off+j] * W[j][k] -------
__global__ void precompute_M_kernel(const float* __restrict__ W_cam,
                                    const float* __restrict__ W_point,
                                    const float* __restrict__ W_final) {
    int n = blockIdx.x;
    int k = threadIdx.x;
    const float* wf = W_final + n * 512;
    float accC = 0.f, accP = 0.f;
#pragma unroll 8
    for (int j = 0; j < D; j++) {
        float c = wf[j];
        float p = wf[256 + j];
        accC = fmaf(c, W_cam[j * D + k], accC);
        accP = fmaf(p, W_point[j * D + k], accP);
    }
    __nv_bfloat16 hc = __float2bfloat16(accC);
    __nv_bfloat16 hp = __float2bfloat16(accP);
    d_Bch[n * D + k] = hc;
    d_Bcl[n * D + k] = __float2bfloat16(accC - __bfloat162float(hc));
    d_Bph[n * D + k] = hp;
    d_Bpl[n * D + k] = __float2bfloat16(accP - __bfloat162float(hp));
}

// v[k] = sum_j W_attn[off+j] * W[j][k]
__global__ void precompute_v_kernel(const float* __restrict__ W_cam,
                                    const float* __restrict__ W_point,
                                    const float* __restrict__ W_attn) {
    int k = threadIdx.x;
    float accC = 0.f, accP = 0.f;
#pragma unroll 8
    for (int j = 0; j < D; j++) {
        accC = fmaf(W_attn[j],       W_cam[j * D + k],   accC);
        accP = fmaf(W_attn[256 + j], W_point[j * D + k], accP);
    }
    d_vc[k] = accC;
    d_vp[k] = accP;
}

// ---------------- scatter-add: 64 threads (float4 lanes) per edge (R3) -------
__global__ __launch_bounds__(256) void scatter_kernel(
        const float4* __restrict__ ef,
        const int* __restrict__ ci,
        const int* __restrict__ pi, int E) {
    int e = blockIdx.x * 4 + (threadIdx.x >> 6);
    int lane = threadIdx.x & 63;
    if (e >= E) return;
    int c = ci[e];
    int p = pi[e];
    float4 v = ef[(size_t)e * 64 + lane];
    red_add_v4(d_cam_agg + c * D + lane * 4, v);
    red_add_v4(d_point_agg + (size_t)p * D + lane * 4, v);
}

// ---------------- fused bf16 split GEMM + rowdot (R3 internals) --------------
// z=0: points, z=1: cams.  C[m][n] = sum_k A[m][k]*B[n][k]; bn==0 blocks also
// emit s[m] = dot(A[m], v) in fp32, computed in the synchronous load phase.
__global__ __launch_bounds__(256) void gemm_fused_kernel() {
    const float* A;
    const __nv_bfloat16 *Bhg, *Blg;
    float* C;
    const float* v;
    float* svec;
    int M;
    if (blockIdx.z == 0) {
        A = d_point_agg; Bhg = d_Bph; Blg = d_Bpl; C = d_g_point;
        v = d_vp; svec = d_s_point; M = NUM_POINTS;
    } else {
        A = d_cam_agg; Bhg = d_Bch; Blg = d_Bcl; C = d_g_cam;
        v = d_vc; svec = d_s_cam; M = NUM_CAMS;
    }
    int bm = blockIdx.x, bn = blockIdx.y;
    if (bm * 128 >= M) return;

    __shared__ __align__(16) __nv_bfloat16 Ah[128][40];
    __shared__ __align__(16) __nv_bfloat16 Al[128][40];
    __shared__ __align__(16) __nv_bfloat16 Bh[128][40];
    __shared__ __align__(16) __nv_bfloat16 Bl[128][40];

    int tid = threadIdx.x;
    int lane = tid & 31;
    int w = tid >> 5;
    int wm = w & 3;          // 4 warps along M
    int wn = w >> 2;         // 2 warps along N

    int ar = tid >> 1;
    int ac = (tid & 1) * 16;
    int am = bm * 128 + ar;
    bool aok = am < M;
    const float4* Ag4 = (const float4*)(A + (size_t)(aok ? am : 0) * 256);
    const uint4* Bh4 = (const uint4*)(Bhg + (size_t)(bn * 128 + ar) * 256);
    const uint4* Bl4 = (const uint4*)(Blg + (size_t)(bn * 128 + ar) * 256);

    float acc[2][8][4];
#pragma unroll
    for (int i = 0; i < 2; i++)
#pragma unroll
        for (int j = 0; j < 8; j++)
#pragma unroll
            for (int q = 0; q < 4; q++) acc[i][j][q] = 0.f;

    float partial = 0.f;   // fused rowdot partial (fp32)

    for (int kc = 0; kc < 8; kc++) {
        int k0 = kc * 32;
        // ---- synchronous load phase (R3): split A hi/lo, accumulate rowdot --
#pragma unroll
        for (int i = 0; i < 4; i++) {
            float4 av = aok ? Ag4[(k0 + ac) / 4 + i] : make_float4(0, 0, 0, 0);
            float vv[4] = {av.x, av.y, av.z, av.w};
#pragma unroll
            for (int q = 0; q < 4; q++) {
                __nv_bfloat16 h = __float2bfloat16(vv[q]);
                Ah[ar][ac + i * 4 + q] = h;
                Al[ar][ac + i * 4 + q] = __float2bfloat16(vv[q] - __bfloat162float(h));
                partial = fmaf(vv[q], __ldg(v + k0 + ac + i * 4 + q), partial);
            }
        }
        {
            int bidx = (k0 + ac) / 8;
            uint4 h0 = Bh4[bidx], h1 = Bh4[bidx + 1];
            uint4 l0 = Bl4[bidx], l1 = Bl4[bidx + 1];
            ((uint4*)&Bh[ar][ac])[0] = h0;
            ((uint4*)&Bh[ar][ac])[1] = h1;
            ((uint4*)&Bl[ar][ac])[0] = l0;
            ((uint4*)&Bl[ar][ac])[1] = l1;
        }
        __syncthreads();

#pragma unroll
        for (int ks = 0; ks < 32; ks += 16) {
            uint32_t fah[2][4], fal[2][4];
#pragma unroll
            for (int mt = 0; mt < 2; mt++) {
                int row = wm * 32 + mt * 16 + (lane & 15);
                int kk = ks + (lane >> 4) * 8;
                uint32_t adh = (uint32_t)__cvta_generic_to_shared(&Ah[row][kk]);
                uint32_t adl = (uint32_t)__cvta_generic_to_shared(&Al[row][kk]);
                asm volatile("ldmatrix.sync.aligned.m8n8.x4.shared.b16 {%0,%1,%2,%3}, [%4];"
                             : "=r"(fah[mt][0]), "=r"(fah[mt][1]), "=r"(fah[mt][2]), "=r"(fah[mt][3])
                             : "r"(adh));
                asm volatile("ldmatrix.sync.aligned.m8n8.x4.shared.b16 {%0,%1,%2,%3}, [%4];"
                             : "=r"(fal[mt][0]), "=r"(fal[mt][1]), "=r"(fal[mt][2]), "=r"(fal[mt][3])
                             : "r"(adl));
            }
            uint32_t fbh[8][2], fbl[8][2];
#pragma unroll
            for (int j = 0; j < 4; j++) {
                int nrow = wn * 64 + j * 16 + ((lane >> 4) & 1) * 8 + (lane & 7);
                int kk = ks + ((lane >> 3) & 1) * 8;
                uint32_t adh = (uint32_t)__cvta_generic_to_shared(&Bh[nrow][kk]);
                uint32_t adl = (uint32_t)__cvta_generic_to_shared(&Bl[nrow][kk]);
                asm volatile("ldmatrix.sync.aligned.m8n8.x4.shared.b16 {%0,%1,%2,%3}, [%4];"
                             : "=r"(fbh[2*j][0]), "=r"(fbh[2*j][1]), "=r"(fbh[2*j+1][0]), "=r"(fbh[2*j+1][1])
                             : "r"(adh));
                asm volatile("ldmatrix.sync.aligned.m8n8.x4.shared.b16 {%0,%1,%2,%3}, [%4];"
                             : "=r"(fbl[2*j][0]), "=r"(fbl[2*j][1]), "=r"(fbl[2*j+1][0]), "=r"(fbl[2*j+1][1])
                             : "r"(adl));
            }
#pragma unroll
            for (int mt = 0; mt < 2; mt++) {
#pragma unroll
                for (int nt = 0; nt < 8; nt++) {
                    float* c = acc[mt][nt];
                    asm volatile(
                        "mma.sync.aligned.m16n8k16.row.col.f32.bf16.bf16.f32 "
                        "{%0,%1,%2,%3},{%4,%5,%6,%7},{%8,%9},{%0,%1,%2,%3};"
                        : "+f"(c[0]), "+f"(c[1]), "+f"(c[2]), "+f"(c[3])
                        : "r"(fah[mt][0]), "r"(fah[mt][1]), "r"(fah[mt][2]), "r"(fah[mt][3]),
                          "r"(fbh[nt][0]), "r"(fbh[nt][1]));
                    asm volatile(
                        "mma.sync.aligned.m16n8k16.row.col.f32.bf16.bf16.f32 "
                        "{%0,%1,%2,%3},{%4,%5,%6,%7},{%8,%9},{%0,%1,%2,%3};"
                        : "+f"(c[0]), "+f"(c[1]), "+f"(c[2]), "+f"(c[3])
                        : "r"(fah[mt][0]), "r"(fah[mt][1]), "r"(fah[mt][2]), "r"(fah[mt][3]),
                          "r"(fbl[nt][0]), "r"(fbl[nt][1]));
                    asm volatile(
                        "mma.sync.aligned.m16n8k16.row.col.f32.bf16.bf16.f32 "
                        "{%0,%1,%2,%3},{%4,%5,%6,%7},{%8,%9},{%0,%1,%2,%3};"
                        : "+f"(c[0]), "+f"(c[1]), "+f"(c[2]), "+f"(c[3])
                        : "r"(fal[mt][0]), "r"(fal[mt][1]), "r"(fal[mt][2]), "r"(fal[mt][3]),
                          "r"(fbh[nt][0]), "r"(fbh[nt][1]));
                }
            }
        }
        __syncthreads();
    }

    // fused rowdot output (bn==0 only; combine the two half-row partials)
    if (bn == 0) {
        float other = __shfl_xor_sync(0xffffffffu, partial, 1);
        if ((tid & 1) == 0 && aok) svec[am] = partial + other;
    }

    // epilogue
#pragma unroll
    for (int mt = 0; mt < 2; mt++) {
        int r0 = bm * 128 + wm * 32 + mt * 16 + (lane >> 2);
#pragma unroll
        for (int nt = 0; nt < 8; nt++) {
            int col = bn * 128 + wn * 64 + nt * 8 + (lane & 3) * 2;
            if (r0 < M)
                *(float2*)&C[(size_t)r0 * 256 + col] =
                    make_float2(acc[mt][nt][0], acc[mt][nt][1]);
            if (r0 + 8 < M)
                *(float2*)&C[(size_t)(r0 + 8) * 256 + col] =
                    make_float2(acc[mt][nt][2], acc[mt][nt][3]);
        }
    }
}

// ---------------- softmax pass 1: score + global max -------------------------
__global__ __launch_bounds__(256) void score_max_kernel(
        const int* __restrict__ ci, const int* __restrict__ pi, int E) {
    int i = blockIdx.x * blockDim.x + threadIdx.x;
    float sc = -3.0e38f;
    if (i < E) {
        sc = d_s_cam[ci[i]] + d_s_point[pi[i]];
        d_score[i] = sc;
    }
#pragma unroll
    for (int o = 16; o; o >>= 1) sc = fmaxf(sc, __shfl_xor_sync(0xffffffffu, sc, o));
    __shared__ float sm[8];
    int w = threadIdx.x >> 5, l = threadIdx.x & 31;
    if (l == 0) sm[w] = sc;
    __syncthreads();
    if (threadIdx.x == 0) {
        float m = sm[0];
#pragma unroll
        for (int k = 1; k < 8; k++) m = fmaxf(m, sm[k]);
        atomicMax(&d_gmax_u, fenc(m));
    }
}

// ---------------- softmax pass 2: exp + global sum ---------------------------
__global__ __launch_bounds__(256) void exp_sum_kernel(int E) {
    int i = blockIdx.x * blockDim.x + threadIdx.x;
    float gmax = fdec(d_gmax_u);
    float v = 0.f;
    if (i < E) {
        v = __expf(d_score[i] - gmax);
        d_expv[i] = v;
    }
#pragma unroll
    for (int o = 16; o; o >>= 1) v += __shfl_xor_sync(0xffffffffu, v, o);
    __shared__ float sm[8];
    int w = threadIdx.x >> 5, l = threadIdx.x & 31;
    if (l == 0) sm[w] = v;
    __syncthreads();
    if (threadIdx.x == 0) {
        float s = 0.f;
#pragma unroll
        for (int k = 0; k < 8; k++) s += sm[k];
        atomicAdd(&d_gsum, s);
    }
}

// ---------------- final: gather + bias + attn scale + relu -------------------
__global__ __launch_bounds__(256) void finalize_kernel(
        const int* __restrict__ ci, const int* __restrict__ pi,
        const float* __restrict__ bfin, float* __restrict__ out, int E) {
    int e = blockIdx.x * 4 + (threadIdx.x >> 6);
    int lane = threadIdx.x & 63;
    if (e >= E) return;
    float a = d_expv[e] * (1.0f / d_gsum);
    int c = ci[e];
    int p = pi[e];
    const float4* gc = (const float4*)(d_g_cam + c * D);
    const float4* gp = (const float4*)(d_g_point + (size_t)p * D);
    const float4* b4 = (const float4*)bfin;
    float4 x = gc[lane], y = gp[lane], z = b4[lane];
    float4 r;
    r.x = fmaxf((x.x + y.x + z.x) * a, 0.f);
    r.y = fmaxf((x.y + y.y + z.y) * a, 0.f);
    r.z = fmaxf((x.z + y.z + z.z) * a, 0.f);
    r.w = fmaxf((x.w + y.w + z.w) * a, 0.f);
    ((float4*)out)[(size_t)e * 64 + lane] = r;
}

// ---------------- launch -----------------------------------------------------
extern "C" void kernel_launch(void* const* d_in, const int* in_sizes, int n_in,
                              void* d_out, int out_size) {
    const float* ef = (const float*)d_in[0];
    const int* ci = (const int*)d_in[1];
    const int* pi = (const int*)d_in[2];

    // skip scalar inputs (num_cams / num_points) if present
    int w = 3;
    while (w < n_in && in_sizes[w] <= 1) w++;
    const float* W_cam   = (const float*)d_in[w + 0];
    const float* W_point = (const float*)d_in[w + 1];
    const float* W_attn  = (const float*)d_in[w + 2];
    const float* W_final = (const float*)d_in[w + 3];
    const float* b_final = (const float*)d_in[w + 4];

    int E = in_sizes[1];
    float* out = (float*)d_out;

    void *pCamAgg, *pPointAgg;
    cudaGetSymbolAddress(&pCamAgg, d_cam_agg);
    cudaGetSymbolAddress(&pPointAgg, d_point_agg);

    cudaMemsetAsync(pCamAgg, 0, sizeof(float) * NUM_CAMS * D);
    cudaMemsetAsync(pPointAgg, 0, sizeof(float) * (size_t)NUM_POINTS * D);
    init_scalars_kernel<<<1, 1>>>();

    precompute_M_kernel<<<256, 256>>>(W_cam, W_point, W_final);
    precompute_v_kernel<<<1, 256>>>(W_cam, W_point, W_attn);

    scatter_kernel<<<(E + 3) / 4, 256>>>((const float4*)ef, ci, pi, E);

    gemm_fused_kernel<<<dim3((NUM_POINTS + 127) / 128, 2, 2), 256>>>();

    score_max_kernel<<<(E + 255) / 256, 256>>>(ci, pi, E);
    exp_sum_kernel<<<(E + 255) / 256, 256>>>(E);

    finalize_kernel<<<(E + 3) / 4, 256>>>(ci, pi, b_final, out, E);
}

// round 10
// speedup vs baseline: 1.1621x; 1.1621x over previous
#include <cuda_runtime.h>
#include <cuda_bf16.h>
#include <cstdint>

#define NUM_CAMS   500
#define NUM_POINTS 100000
#define MAX_E      250000
#define D          256

// ---------------- scratch (device globals; no allocations allowed) ----------
__device__ float d_cam_agg[NUM_CAMS * D];
__device__ float d_point_agg[NUM_POINTS * D];
__device__ float d_g_cam[NUM_CAMS * D];
__device__ float d_g_point[NUM_POINTS * D];
__device__ float d_s_cam[NUM_CAMS];
__device__ float d_s_point[NUM_POINTS];
// fused weight matrices, bf16 hi/lo split, [n][k] layout (k contiguous)
__device__ __nv_bfloat16 d_Bch[D * D];
__device__ __nv_bfloat16 d_Bcl[D * D];
__device__ __nv_bfloat16 d_Bph[D * D];
__device__ __nv_bfloat16 d_Bpl[D * D];
__device__ float d_vc[D];
__device__ float d_vp[D];
__device__ float d_score[MAX_E];
__device__ float d_expv[MAX_E];
__device__ unsigned int d_gmax_u;
__device__ float d_gsum;

// ---------------- helpers ----------------------------------------------------
__device__ __forceinline__ unsigned int fenc(float f) {
    unsigned int u = __float_as_uint(f);
    return (u & 0x80000000u) ? ~u : (u | 0x80000000u);
}
__device__ __forceinline__ float fdec(unsigned int x) {
    return (x & 0x80000000u) ? __uint_as_float(x & 0x7fffffffu)
                             : __uint_as_float(~x);
}

__device__ __forceinline__ void red_add_v4(float* p, float4 v) {
    asm volatile("red.global.add.v4.f32 [%0], {%1, %2, %3, %4};"
                 :: "l"(p), "f"(v.x), "f"(v.y), "f"(v.z), "f"(v.w)
                 : "memory");
}

__global__ void init_scalars_kernel() {
    d_gmax_u = 0u;     // encodes -inf
    d_gsum = 0.0f;
}

// ---------------- fold weights: M[n][k] = sum_j Wf[n][off+j] * W[j][k] -------
__global__ void precompute_M_kernel(const float* __restrict__ W_cam,
                                    const float* __restrict__ W_point,
                                    const float* __restrict__ W_final) {
    int n = blockIdx.x;
    int k = threadIdx.x;
    const float* wf = W_final + n * 512;
    float accC = 0.f, accP = 0.f;
#pragma unroll 8
    for (int j = 0; j < D; j++) {
        float c = wf[j];
        float p = wf[256 + j];
        accC = fmaf(c, W_cam[j * D + k], accC);
        accP = fmaf(p, W_point[j * D + k], accP);
    }
    __nv_bfloat16 hc = __float2bfloat16(accC);
    __nv_bfloat16 hp = __float2bfloat16(accP);
    d_Bch[n * D + k] = hc;
    d_Bcl[n * D + k] = __float2bfloat16(accC - __bfloat162float(hc));
    d_Bph[n * D + k] = hp;
    d_Bpl[n * D + k] = __float2bfloat16(accP - __bfloat162float(hp));
}

// v[k] = sum_j W_attn[off+j] * W[j][k]
__global__ void precompute_v_kernel(const float* __restrict__ W_cam,
                                    const float* __restrict__ W_point,
                                    const float* __restrict__ W_attn) {
    int k = threadIdx.x;
    float accC = 0.f, accP = 0.f;
#pragma unroll 8
    for (int j = 0; j < D; j++) {
        accC = fmaf(W_attn[j],       W_cam[j * D + k],   accC);
        accP = fmaf(W_attn[256 + j], W_point[j * D + k], accP);
    }
    d_vc[k] = accC;
    d_vp[k] = accP;
}

// ---------------- scatter-add: 64 threads (float4 lanes) per edge ------------
__global__ __launch_bounds__(256) void scatter_kernel(
        const float4* __restrict__ ef,
        const int* __restrict__ ci,
        const int* __restrict__ pi, int E) {
    int e = blockIdx.x * 4 + (threadIdx.x >> 6);
    int lane = threadIdx.x & 63;
    if (e >= E) return;
    int c = ci[e];
    int p = pi[e];
    float4 v = ef[(size_t)e * 64 + lane];
    red_add_v4(d_cam_agg + c * D + lane * 4, v);
    red_add_v4(d_point_agg + (size_t)p * D + lane * 4, v);
}

// ---------------- bf16 split-precision tensor-core GEMM + reg prefetch -------
// C[m][n] = sum_k A[m][k] * B[n][k],  K = 256, N = 256.
// Identical to R3 except: next BK=32 chunk is prefetched into registers
// while the MMAs consume the current smem tiles.
__global__ __launch_bounds__(256) void gemm_bf16_kernel(
        const float* __restrict__ A,
        const __nv_bfloat16* __restrict__ Bhg,
        const __nv_bfloat16* __restrict__ Blg,
        float* __restrict__ C, int M) {
    __shared__ __align__(16) __nv_bfloat16 Ah[128][40];
    __shared__ __align__(16) __nv_bfloat16 Al[128][40];
    __shared__ __align__(16) __nv_bfloat16 Bh[128][40];
    __shared__ __align__(16) __nv_bfloat16 Bl[128][40];

    int tid = threadIdx.x;
    int bm = blockIdx.x, bn = blockIdx.y;
    int lane = tid & 31;
    int w = tid >> 5;
    int wm = w & 3;          // 4 warps along M
    int wn = w >> 2;         // 2 warps along N

    int ar = tid >> 1;
    int ac = (tid & 1) * 16;
    int am = bm * 128 + ar;
    bool aok = am < M;
    const float4* Ag4 = (const float4*)(A + (size_t)(aok ? am : 0) * 256);
    const uint4* Bh4 = (const uint4*)(Bhg + (size_t)(bn * 128 + ar) * 256);
    const uint4* Bl4 = (const uint4*)(Blg + (size_t)(bn * 128 + ar) * 256);

    float acc[2][8][4];
#pragma unroll
    for (int i = 0; i < 2; i++)
#pragma unroll
        for (int j = 0; j < 8; j++)
#pragma unroll
            for (int q = 0; q < 4; q++) acc[i][j][q] = 0.f;

    float4 pa[4];
    uint4 pbh[2], pbl[2];
#pragma unroll
    for (int i = 0; i < 4; i++)
        pa[i] = aok ? Ag4[ac / 4 + i] : make_float4(0, 0, 0, 0);
    pbh[0] = Bh4[ac / 8]; pbh[1] = Bh4[ac / 8 + 1];
    pbl[0] = Bl4[ac / 8]; pbl[1] = Bl4[ac / 8 + 1];

    for (int kc = 0; kc < 8; kc++) {
        // ---- store phase from prefetch registers ----------------------------
#pragma unroll
        for (int i = 0; i < 4; i++) {
            float vv[4] = {pa[i].x, pa[i].y, pa[i].z, pa[i].w};
#pragma unroll
            for (int q = 0; q < 4; q++) {
                __nv_bfloat16 h = __float2bfloat16(vv[q]);
                Ah[ar][ac + i * 4 + q] = h;
                Al[ar][ac + i * 4 + q] = __float2bfloat16(vv[q] - __bfloat162float(h));
            }
        }
        ((uint4*)&Bh[ar][ac])[0] = pbh[0];
        ((uint4*)&Bh[ar][ac])[1] = pbh[1];
        ((uint4*)&Bl[ar][ac])[0] = pbl[0];
        ((uint4*)&Bl[ar][ac])[1] = pbl[1];
        __syncthreads();

        // ---- prefetch next chunk while MMAs run -----------------------------
        if (kc < 7) {
            int kn = (kc + 1) * 32;
#pragma unroll
            for (int i = 0; i < 4; i++)
                pa[i] = aok ? Ag4[(kn + ac) / 4 + i] : make_float4(0, 0, 0, 0);
            pbh[0] = Bh4[(kn + ac) / 8]; pbh[1] = Bh4[(kn + ac) / 8 + 1];
            pbl[0] = Bl4[(kn + ac) / 8]; pbl[1] = Bl4[(kn + ac) / 8 + 1];
        }

#pragma unroll
        for (int ks = 0; ks < 32; ks += 16) {
            uint32_t fah[2][4], fal[2][4];
#pragma unroll
            for (int mt = 0; mt < 2; mt++) {
                int row = wm * 32 + mt * 16 + (lane & 15);
                int kk = ks + (lane >> 4) * 8;
                uint32_t adh = (uint32_t)__cvta_generic_to_shared(&Ah[row][kk]);
                uint32_t adl = (uint32_t)__cvta_generic_to_shared(&Al[row][kk]);
                asm volatile("ldmatrix.sync.aligned.m8n8.x4.shared.b16 {%0,%1,%2,%3}, [%4];"
                             : "=r"(fah[mt][0]), "=r"(fah[mt][1]), "=r"(fah[mt][2]), "=r"(fah[mt][3])
                             : "r"(adh));
                asm volatile("ldmatrix.sync.aligned.m8n8.x4.shared.b16 {%0,%1,%2,%3}, [%4];"
                             : "=r"(fal[mt][0]), "=r"(fal[mt][1]), "=r"(fal[mt][2]), "=r"(fal[mt][3])
                             : "r"(adl));
            }
            uint32_t fbh[8][2], fbl[8][2];
#pragma unroll
            for (int j = 0; j < 4; j++) {
                int nrow = wn * 64 + j * 16 + ((lane >> 4) & 1) * 8 + (lane & 7);
                int kk = ks + ((lane >> 3) & 1) * 8;
                uint32_t adh = (uint32_t)__cvta_generic_to_shared(&Bh[nrow][kk]);
                uint32_t adl = (uint32_t)__cvta_generic_to_shared(&Bl[nrow][kk]);
                asm volatile("ldmatrix.sync.aligned.m8n8.x4.shared.b16 {%0,%1,%2,%3}, [%4];"
                             : "=r"(fbh[2*j][0]), "=r"(fbh[2*j][1]), "=r"(fbh[2*j+1][0]), "=r"(fbh[2*j+1][1])
                             : "r"(adh));
                asm volatile("ldmatrix.sync.aligned.m8n8.x4.shared.b16 {%0,%1,%2,%3}, [%4];"
                             : "=r"(fbl[2*j][0]), "=r"(fbl[2*j][1]), "=r"(fbl[2*j+1][0]), "=r"(fbl[2*j+1][1])
                             : "r"(adl));
            }
#pragma unroll
            for (int mt = 0; mt < 2; mt++) {
#pragma unroll
                for (int nt = 0; nt < 8; nt++) {
                    float* c = acc[mt][nt];
                    asm volatile(
                        "mma.sync.aligned.m16n8k16.row.col.f32.bf16.bf16.f32 "
                        "{%0,%1,%2,%3},{%4,%5,%6,%7},{%8,%9},{%0,%1,%2,%3};"
                        : "+f"(c[0]), "+f"(c[1]), "+f"(c[2]), "+f"(c[3])
                        : "r"(fah[mt][0]), "r"(fah[mt][1]), "r"(fah[mt][2]), "r"(fah[mt][3]),
                          "r"(fbh[nt][0]), "r"(fbh[nt][1]));
                    asm volatile(
                        "mma.sync.aligned.m16n8k16.row.col.f32.bf16.bf16.f32 "
                        "{%0,%1,%2,%3},{%4,%5,%6,%7},{%8,%9},{%0,%1,%2,%3};"
                        : "+f"(c[0]), "+f"(c[1]), "+f"(c[2]), "+f"(c[3])
                        : "r"(fah[mt][0]), "r"(fah[mt][1]), "r"(fah[mt][2]), "r"(fah[mt][3]),
                          "r"(fbl[nt][0]), "r"(fbl[nt][1]));
                    asm volatile(
                        "mma.sync.aligned.m16n8k16.row.col.f32.bf16.bf16.f32 "
                        "{%0,%1,%2,%3},{%4,%5,%6,%7},{%8,%9},{%0,%1,%2,%3};"
                        : "+f"(c[0]), "+f"(c[1]), "+f"(c[2]), "+f"(c[3])
                        : "r"(fal[mt][0]), "r"(fal[mt][1]), "r"(fal[mt][2]), "r"(fal[mt][3]),
                          "r"(fbh[nt][0]), "r"(fbh[nt][1]));
                }
            }
        }
        __syncthreads();
    }

    // epilogue
#pragma unroll
    for (int mt = 0; mt < 2; mt++) {
        int r0 = bm * 128 + wm * 32 + mt * 16 + (lane >> 2);
#pragma unroll
        for (int nt = 0; nt < 8; nt++) {
            int col = bn * 128 + wn * 64 + nt * 8 + (lane & 3) * 2;
            if (r0 < M)
                *(float2*)&C[(size_t)r0 * 256 + col] =
                    make_float2(acc[mt][nt][0], acc[mt][nt][1]);
            if (r0 + 8 < M)
                *(float2*)&C[(size_t)(r0 + 8) * 256 + col] =
                    make_float2(acc[mt][nt][2], acc[mt][nt][3]);
        }
    }
}

// ---------------- s[m] = dot(A[m][:], v) ; one warp per row ------------------
__global__ __launch_bounds__(256) void rowdot_kernel(
        const float* __restrict__ A, const float* __restrict__ v,
        float* __restrict__ s, int M) {
    int warp = (blockIdx.x * blockDim.x + threadIdx.x) >> 5;
    int lane = threadIdx.x & 31;
    if (warp >= M) return;
    const float4* row = (const float4*)(A + (size_t)warp * 256);
    const float4* v4 = (const float4*)v;
    float4 x = row[lane], y = row[lane + 32];
    float4 a = v4[lane], b = v4[lane + 32];
    float acc = x.x * a.x + x.y * a.y + x.z * a.z + x.w * a.w +
                y.x * b.x + y.y * b.y + y.z * b.z + y.w * b.w;
#pragma unroll
    for (int o = 16; o; o >>= 1) acc += __shfl_xor_sync(0xffffffffu, acc, o);
    if (lane == 0) s[warp] = acc;
}

// ---------------- softmax pass 1: score + global max -------------------------
__global__ __launch_bounds__(256) void score_max_kernel(
        const int* __restrict__ ci, const int* __restrict__ pi, int E) {
    int i = blockIdx.x * blockDim.x + threadIdx.x;
    float sc = -3.0e38f;
    if (i < E) {
        sc = d_s_cam[ci[i]] + d_s_point[pi[i]];
        d_score[i] = sc;
    }
#pragma unroll
    for (int o = 16; o; o >>= 1) sc = fmaxf(sc, __shfl_xor_sync(0xffffffffu, sc, o));
    __shared__ float sm[8];
    int w = threadIdx.x >> 5, l = threadIdx.x & 31;
    if (l == 0) sm[w] = sc;
    __syncthreads();
    if (threadIdx.x == 0) {
        float m = sm[0];
#pragma unroll
        for (int k = 1; k < 8; k++) m = fmaxf(m, sm[k]);
        atomicMax(&d_gmax_u, fenc(m));
    }
}

// ---------------- softmax pass 2: exp + global sum ---------------------------
__global__ __launch_bounds__(256) void exp_sum_kernel(int E) {
    int i = blockIdx.x * blockDim.x + threadIdx.x;
    float gmax = fdec(d_gmax_u);
    float v = 0.f;
    if (i < E) {
        v = __expf(d_score[i] - gmax);
        d_expv[i] = v;
    }
#pragma unroll
    for (int o = 16; o; o >>= 1) v += __shfl_xor_sync(0xffffffffu, v, o);
    __shared__ float sm[8];
    int w = threadIdx.x >> 5, l = threadIdx.x & 31;
    if (l == 0) sm[w] = v;
    __syncthreads();
    if (threadIdx.x == 0) {
        float s = 0.f;
#pragma unroll
        for (int k = 0; k < 8; k++) s += sm[k];
        atomicAdd(&d_gsum, s);
    }
}

// ---------------- final: gather + bias + attn scale + relu -------------------
__global__ __launch_bounds__(256) void finalize_kernel(
        const int* __restrict__ ci, const int* __restrict__ pi,
        const float* __restrict__ bfin, float* __restrict__ out, int E) {
    int e = blockIdx.x * 4 + (threadIdx.x >> 6);
    int lane = threadIdx.x & 63;
    if (e >= E) return;
    float a = d_expv[e] * (1.0f / d_gsum);
    int c = ci[e];
    int p = pi[e];
    const float4* gc = (const float4*)(d_g_cam + c * D);
    const float4* gp = (const float4*)(d_g_point + (size_t)p * D);
    const float4* b4 = (const float4*)bfin;
    float4 x = gc[lane], y = gp[lane], z = b4[lane];
    float4 r;
    r.x = fmaxf((x.x + y.x + z.x) * a, 0.f);
    r.y = fmaxf((x.y + y.y + z.y) * a, 0.f);
    r.z = fmaxf((x.z + y.z + z.z) * a, 0.f);
    r.w = fmaxf((x.w + y.w + z.w) * a, 0.f);
    ((float4*)out)[(size_t)e * 64 + lane] = r;
}

// ---------------- launch -----------------------------------------------------
extern "C" void kernel_launch(void* const* d_in, const int* in_sizes, int n_in,
                              void* d_out, int out_size) {
    const float* ef = (const float*)d_in[0];
    const int* ci = (const int*)d_in[1];
    const int* pi = (const int*)d_in[2];

    // skip scalar inputs (num_cams / num_points) if present
    int w = 3;
    while (w < n_in && in_sizes[w] <= 1) w++;
    const float* W_cam   = (const float*)d_in[w + 0];
    const float* W_point = (const float*)d_in[w + 1];
    const float* W_attn  = (const float*)d_in[w + 2];
    const float* W_final = (const float*)d_in[w + 3];
    const float* b_final = (const float*)d_in[w + 4];

    int E = in_sizes[1];
    float* out = (float*)d_out;

    void *pCamAgg, *pPointAgg, *pGCam, *pGPoint, *pSCam, *pSPoint;
    void *pBch, *pBcl, *pBph, *pBpl, *pVc, *pVp;
    cudaGetSymbolAddress(&pCamAgg, d_cam_agg);
    cudaGetSymbolAddress(&pPointAgg, d_point_agg);
    cudaGetSymbolAddress(&pGCam, d_g_cam);
    cudaGetSymbolAddress(&pGPoint, d_g_point);
    cudaGetSymbolAddress(&pSCam, d_s_cam);
    cudaGetSymbolAddress(&pSPoint, d_s_point);
    cudaGetSymbolAddress(&pBch, d_Bch);
    cudaGetSymbolAddress(&pBcl, d_Bcl);
    cudaGetSymbolAddress(&pBph, d_Bph);
    cudaGetSymbolAddress(&pBpl, d_Bpl);
    cudaGetSymbolAddress(&pVc, d_vc);
    cudaGetSymbolAddress(&pVp, d_vp);

    cudaMemsetAsync(pCamAgg, 0, sizeof(float) * NUM_CAMS * D);
    cudaMemsetAsync(pPointAgg, 0, sizeof(float) * (size_t)NUM_POINTS * D);
    init_scalars_kernel<<<1, 1>>>();

    precompute_M_kernel<<<256, 256>>>(W_cam, W_point, W_final);
    precompute_v_kernel<<<1, 256>>>(W_cam, W_point, W_attn);

    scatter_kernel<<<(E + 3) / 4, 256>>>((const float4*)ef, ci, pi, E);

    gemm_bf16_kernel<<<dim3((NUM_POINTS + 127) / 128, 2), 256>>>(
        (const float*)pPointAgg, (const __nv_bfloat16*)pBph,
        (const __nv_bfloat16*)pBpl, (float*)pGPoint, NUM_POINTS);
    gemm_bf16_kernel<<<dim3((NUM_CAMS + 127) / 128, 2), 256>>>(
        (const float*)pCamAgg, (const __nv_bfloat16*)pBch,
        (const __nv_bfloat16*)pBcl, (float*)pGCam, NUM_CAMS);

    rowdot_kernel<<<(NUM_POINTS * 32 + 255) / 256, 256>>>(
        (const float*)pPointAgg, (const float*)pVp, (float*)pSPoint, NUM_POINTS);
    rowdot_kernel<<<(NUM_CAMS * 32 + 255) / 256, 256>>>(
        (const float*)pCamAgg, (const float*)pVc, (float*)pSCam, NUM_CAMS);

    score_max_kernel<<<(E + 255) / 256, 256>>>(ci, pi, E);
    exp_sum_kernel<<<(E + 255) / 256, 256>>>(E);

    finalize_kernel<<<(E + 3) / 4, 256>>>(ci, pi, b_final, out, E);
}

// round 13
// speedup vs baseline: 1.1930x; 1.0266x over previous
#include <cuda_runtime.h>
#include <cuda_bf16.h>
#include <cstdint>

#define NUM_CAMS   500
#define NUM_POINTS 100000
#define MAX_E      250000
#define D          256

// ---------------- scratch (device globals; no allocations allowed) ----------
__device__ float d_cam_agg[NUM_CAMS * D];
__device__ float d_point_agg[NUM_POINTS * D];
__device__ float d_g_cam[NUM_CAMS * D];
__device__ float d_g_point[NUM_POINTS * D];
__device__ float d_s_cam[NUM_CAMS];
__device__ float d_s_point[NUM_POINTS];
// fused weight matrices, bf16 hi/lo split, [n][k] layout (k contiguous)
__device__ __align__(16) __nv_bfloat16 d_Bch[D * D];
__device__ __align__(16) __nv_bfloat16 d_Bcl[D * D];
__device__ __align__(16) __nv_bfloat16 d_Bph[D * D];
__device__ __align__(16) __nv_bfloat16 d_Bpl[D * D];
__device__ float d_vc[D];
__device__ float d_vp[D];
__device__ float d_score[MAX_E];
__device__ float d_expv[MAX_E];
__device__ unsigned int d_gmax_u;
__device__ float d_gsum;

// ---------------- helpers ----------------------------------------------------
__device__ __forceinline__ unsigned int fenc(float f) {
    unsigned int u = __float_as_uint(f);
    return (u & 0x80000000u) ? ~u : (u | 0x80000000u);
}
__device__ __forceinline__ float fdec(unsigned int x) {
    return (x & 0x80000000u) ? __uint_as_float(x & 0x7fffffffu)
                             : __uint_as_float(~x);
}

__device__ __forceinline__ void red_add_v4(float* p, float4 v) {
    asm volatile("red.global.add.v4.f32 [%0], {%1, %2, %3, %4};"
                 :: "l"(p), "f"(v.x), "f"(v.y), "f"(v.z), "f"(v.w)
                 : "memory");
}

__global__ void init_scalars_kernel() {
    d_gmax_u = 0u;     // encodes -inf
    d_gsum = 0.0f;
}

// ================= STAGE 1: precompute (blocks 0..256) + scatter =============
__global__ __launch_bounds__(256) void stage1_kernel(
        const float4* __restrict__ ef,
        const int* __restrict__ ci,
        const int* __restrict__ pi,
        const float* __restrict__ W_cam,
        const float* __restrict__ W_point,
        const float* __restrict__ W_attn,
        const float* __restrict__ W_final,
        int E) {
    if (blockIdx.x < 256) {
        // ---- precompute_M: M[n][k] = sum_j Wf[n][off+j] * W[j][k] ----------
        int n = blockIdx.x;
        int k = threadIdx.x;
        const float* wf = W_final + n * 512;
        float accC = 0.f, accP = 0.f;
#pragma unroll 8
        for (int j = 0; j < D; j++) {
            float c = wf[j];
            float p = wf[256 + j];
            accC = fmaf(c, W_cam[j * D + k], accC);
            accP = fmaf(p, W_point[j * D + k], accP);
        }
        __nv_bfloat16 hc = __float2bfloat16(accC);
        __nv_bfloat16 hp = __float2bfloat16(accP);
        d_Bch[n * D + k] = hc;
        d_Bcl[n * D + k] = __float2bfloat16(accC - __bfloat162float(hc));
        d_Bph[n * D + k] = hp;
        d_Bpl[n * D + k] = __float2bfloat16(accP - __bfloat162float(hp));
    } else if (blockIdx.x == 256) {
        // ---- precompute_v: v[k] = sum_j W_attn[off+j] * W[j][k] ------------
        int k = threadIdx.x;
        float accC = 0.f, accP = 0.f;
#pragma unroll 8
        for (int j = 0; j < D; j++) {
            accC = fmaf(W_attn[j],       W_cam[j * D + k],   accC);
            accP = fmaf(W_attn[256 + j], W_point[j * D + k], accP);
        }
        d_vc[k] = accC;
        d_vp[k] = accP;
    } else {
        // ---- scatter: 64 threads (float4 lanes) per edge -------------------
        int e = (blockIdx.x - 257) * 4 + (threadIdx.x >> 6);
        int lane = threadIdx.x & 63;
        if (e >= E) return;
        int c = ci[e];
        int p = pi[e];
        float4 v = ef[(size_t)e * 64 + lane];
        red_add_v4(d_cam_agg + c * D + lane * 4, v);
        red_add_v4(d_point_agg + (size_t)p * D + lane * 4, v);
    }
}

// ================= STAGE 2: GEMMs + rowdots in one launch ====================
// bf16 split-precision tensor-core GEMM (validated R10 internals).
// C[m][n] = sum_k A[m][k]*B[n][k], K=N=256; 3-term hi/lo split; reg prefetch.
__device__ __forceinline__ void gemm_dev(
        const float* __restrict__ A,
        const __nv_bfloat16* __restrict__ Bhg,
        const __nv_bfloat16* __restrict__ Blg,
        float* __restrict__ C, int M, int bm, int bn) {
    __shared__ __align__(16) __nv_bfloat16 Ah[128][40];
    __shared__ __align__(16) __nv_bfloat16 Al[128][40];
    __shared__ __align__(16) __nv_bfloat16 Bh[128][40];
    __shared__ __align__(16) __nv_bfloat16 Bl[128][40];

    int tid = threadIdx.x;
    int lane = tid & 31;
    int w = tid >> 5;
    int wm = w & 3;          // 4 warps along M
    int wn = w >> 2;         // 2 warps along N

    int ar = tid >> 1;
    int ac = (tid & 1) * 16;
    int am = bm * 128 + ar;
    bool aok = am < M;
    const float4* Ag4 = (const float4*)(A + (size_t)(aok ? am : 0) * 256);
    const uint4* Bh4 = (const uint4*)(Bhg + (size_t)(bn * 128 + ar) * 256);
    const uint4* Bl4 = (const uint4*)(Blg + (size_t)(bn * 128 + ar) * 256);

    float acc[2][8][4];
#pragma unroll
    for (int i = 0; i < 2; i++)
#pragma unroll
        for (int j = 0; j < 8; j++)
#pragma unroll
            for (int q = 0; q < 4; q++) acc[i][j][q] = 0.f;

    float4 pa[4];
    uint4 pbh[2], pbl[2];
#pragma unroll
    for (int i = 0; i < 4; i++)
        pa[i] = aok ? Ag4[ac / 4 + i] : make_float4(0, 0, 0, 0);
    pbh[0] = Bh4[ac / 8]; pbh[1] = Bh4[ac / 8 + 1];
    pbl[0] = Bl4[ac / 8]; pbl[1] = Bl4[ac / 8 + 1];

    for (int kc = 0; kc < 8; kc++) {
#pragma unroll
        for (int i = 0; i < 4; i++) {
            float vv[4] = {pa[i].x, pa[i].y, pa[i].z, pa[i].w};
#pragma unroll
            for (int q = 0; q < 4; q++) {
                __nv_bfloat16 h = __float2bfloat16(vv[q]);
                Ah[ar][ac + i * 4 + q] = h;
                Al[ar][ac + i * 4 + q] = __float2bfloat16(vv[q] - __bfloat162float(h));
            }
        }
        ((uint4*)&Bh[ar][ac])[0] = pbh[0];
        ((uint4*)&Bh[ar][ac])[1] = pbh[1];
        ((uint4*)&Bl[ar][ac])[0] = pbl[0];
        ((uint4*)&Bl[ar][ac])[1] = pbl[1];
        __syncthreads();

        if (kc < 7) {
            int kn = (kc + 1) * 32;
#pragma unroll
            for (int i = 0; i < 4; i++)
                pa[i] = aok ? Ag4[(kn + ac) / 4 + i] : make_float4(0, 0, 0, 0);
            pbh[0] = Bh4[(kn + ac) / 8]; pbh[1] = Bh4[(kn + ac) / 8 + 1];
            pbl[0] = Bl4[(kn + ac) / 8]; pbl[1] = Bl4[(kn + ac) / 8 + 1];
        }

#pragma unroll
        for (int ks = 0; ks < 32; ks += 16) {
            uint32_t fah[2][4], fal[2][4];
#pragma unroll
            for (int mt = 0; mt < 2; mt++) {
                int row = wm * 32 + mt * 16 + (lane & 15);
                int kk = ks + (lane >> 4) * 8;
                uint32_t adh = (uint32_t)__cvta_generic_to_shared(&Ah[row][kk]);
                uint32_t adl = (uint32_t)__cvta_generic_to_shared(&Al[row][kk]);
                asm volatile("ldmatrix.sync.aligned.m8n8.x4.shared.b16 {%0,%1,%2,%3}, [%4];"
                             : "=r"(fah[mt][0]), "=r"(fah[mt][1]), "=r"(fah[mt][2]), "=r"(fah[mt][3])
                             : "r"(adh));
                asm volatile("ldmatrix.sync.aligned.m8n8.x4.shared.b16 {%0,%1,%2,%3}, [%4];"
                             : "=r"(fal[mt][0]), "=r"(fal[mt][1]), "=r"(fal[mt][2]), "=r"(fal[mt][3])
                             : "r"(adl));
            }
            uint32_t fbh[8][2], fbl[8][2];
#pragma unroll
            for (int j = 0; j < 4; j++) {
                int nrow = wn * 64 + j * 16 + ((lane >> 4) & 1) * 8 + (lane & 7);
                int kk = ks + ((lane >> 3) & 1) * 8;
                uint32_t adh = (uint32_t)__cvta_generic_to_shared(&Bh[nrow][kk]);
                uint32_t adl = (uint32_t)__cvta_generic_to_shared(&Bl[nrow][kk]);
                asm volatile("ldmatrix.sync.aligned.m8n8.x4.shared.b16 {%0,%1,%2,%3}, [%4];"
                             : "=r"(fbh[2*j][0]), "=r"(fbh[2*j][1]), "=r"(fbh[2*j+1][0]), "=r"(fbh[2*j+1][1])
                             : "r"(adh));
                asm volatile("ldmatrix.sync.aligned.m8n8.x4.shared.b16 {%0,%1,%2,%3}, [%4];"
                             : "=r"(fbl[2*j][0]), "=r"(fbl[2*j][1]), "=r"(fbl[2*j+1][0]), "=r"(fbl[2*j+1][1])
                             : "r"(adl));
            }
#pragma unroll
            for (int mt = 0; mt < 2; mt++) {
#pragma unroll
                for (int nt = 0; nt < 8; nt++) {
                    float* c = acc[mt][nt];
                    asm volatile(
                        "mma.sync.aligned.m16n8k16.row.col.f32.bf16.bf16.f32 "
                        "{%0,%1,%2,%3},{%4,%5,%6,%7},{%8,%9},{%0,%1,%2,%3};"
                        : "+f"(c[0]), "+f"(c[1]), "+f"(c[2]), "+f"(c[3])
                        : "r"(fah[mt][0]), "r"(fah[mt][1]), "r"(fah[mt][2]), "r"(fah[mt][3]),
                          "r"(fbh[nt][0]), "r"(fbh[nt][1]));
                    asm volatile(
                        "mma.sync.aligned.m16n8k16.row.col.f32.bf16.bf16.f32 "
                        "{%0,%1,%2,%3},{%4,%5,%6,%7},{%8,%9},{%0,%1,%2,%3};"
                        : "+f"(c[0]), "+f"(c[1]), "+f"(c[2]), "+f"(c[3])
                        : "r"(fah[mt][0]), "r"(fah[mt][1]), "r"(fah[mt][2]), "r"(fah[mt][3]),
                          "r"(fbl[nt][0]), "r"(fbl[nt][1]));
                    asm volatile(
                        "mma.sync.aligned.m16n8k16.row.col.f32.bf16.bf16.f32 "
                        "{%0,%1,%2,%3},{%4,%5,%6,%7},{%8,%9},{%0,%1,%2,%3};"
                        : "+f"(c[0]), "+f"(c[1]), "+f"(c[2]), "+f"(c[3])
                        : "r"(fal[mt][0]), "r"(fal[mt][1]), "r"(fal[mt][2]), "r"(fal[mt][3]),
                          "r"(fbh[nt][0]), "r"(fbh[nt][1]));
                }
            }
        }
        __syncthreads();
    }

#pragma unroll
    for (int mt = 0; mt < 2; mt++) {
        int r0 = bm * 128 + wm * 32 + mt * 16 + (lane >> 2);
#pragma unroll
        for (int nt = 0; nt < 8; nt++) {
            int col = bn * 128 + wn * 64 + nt * 8 + (lane & 3) * 2;
            if (r0 < M)
                *(float2*)&C[(size_t)r0 * 256 + col] =
                    make_float2(acc[mt][nt][0], acc[mt][nt][1]);
            if (r0 + 8 < M)
                *(float2*)&C[(size_t)(r0 + 8) * 256 + col] =
                    make_float2(acc[mt][nt][2], acc[mt][nt][3]);
        }
    }
}

// rowdot: s[m] = dot(A[m][:], v); one warp per row, blk = local block index
__device__ __forceinline__ void rowdot_dev(
        const float* __restrict__ A, const float* __restrict__ v,
        float* __restrict__ s, int M, int blk) {
    int warp = (blk * 256 + threadIdx.x) >> 5;
    int lane = threadIdx.x & 31;
    if (warp >= M) return;
    const float4* row = (const float4*)(A + (size_t)warp * 256);
    const float4* v4 = (const float4*)v;
    float4 x = row[lane], y = row[lane + 32];
    float4 a = v4[lane], b = v4[lane + 32];
    float acc = x.x * a.x + x.y * a.y + x.z * a.z + x.w * a.w +
                y.x * b.x + y.y * b.y + y.z * b.z + y.w * b.w;
#pragma unroll
    for (int o = 16; o; o >>= 1) acc += __shfl_xor_sync(0xffffffffu, acc, o);
    if (lane == 0) s[warp] = acc;
}

#define NPG (((NUM_POINTS + 127) / 128) * 2)     // 1564 point-GEMM blocks
#define NCG (((NUM_CAMS + 127) / 128) * 2)       // 8 cam-GEMM blocks
#define NRP ((NUM_POINTS * 32 + 255) / 256)      // 12500 point rowdot blocks
#define NRC ((NUM_CAMS * 32 + 255) / 256)        // 63 cam rowdot blocks

__global__ __launch_bounds__(256) void stage2_kernel() {
    int b = blockIdx.x;
    if (b < NPG) {
        gemm_dev(d_point_agg, d_Bph, d_Bpl, d_g_point, NUM_POINTS, b >> 1, b & 1);
    } else if (b < NPG + NCG) {
        int t = b - NPG;
        gemm_dev(d_cam_agg, d_Bch, d_Bcl, d_g_cam, NUM_CAMS, t >> 1, t & 1);
    } else if (b < NPG + NCG + NRP) {
        rowdot_dev(d_point_agg, d_vp, d_s_point, NUM_POINTS, b - NPG - NCG);
    } else {
        rowdot_dev(d_cam_agg, d_vc, d_s_cam, NUM_CAMS, b - NPG - NCG - NRP);
    }
}

// ---------------- softmax pass 1: score + global max -------------------------
__global__ __launch_bounds__(256) void score_max_kernel(
        const int* __restrict__ ci, const int* __restrict__ pi, int E) {
    int i = blockIdx.x * blockDim.x + threadIdx.x;
    float sc = -3.0e38f;
    if (i < E) {
        sc = d_s_cam[ci[i]] + d_s_point[pi[i]];
        d_score[i] = sc;
    }
#pragma unroll
    for (int o = 16; o; o >>= 1) sc = fmaxf(sc, __shfl_xor_sync(0xffffffffu, sc, o));
    __shared__ float sm[8];
    int w = threadIdx.x >> 5, l = threadIdx.x & 31;
    if (l == 0) sm[w] = sc;
    __syncthreads();
    if (threadIdx.x == 0) {
        float m = sm[0];
#pragma unroll
        for (int k = 1; k < 8; k++) m = fmaxf(m, sm[k]);
        atomicMax(&d_gmax_u, fenc(m));
    }
}

// ---------------- softmax pass 2: exp + global sum ---------------------------
__global__ __launch_bounds__(256) void exp_sum_kernel(int E) {
    int i = blockIdx.x * blockDim.x + threadIdx.x;
    float gmax = fdec(d_gmax_u);
    float v = 0.f;
    if (i < E) {
        v = __expf(d_score[i] - gmax);
        d_expv[i] = v;
    }
#pragma unroll
    for (int o = 16; o; o >>= 1) v += __shfl_xor_sync(0xffffffffu, v, o);
    __shared__ float sm[8];
    int w = threadIdx.x >> 5, l = threadIdx.x & 31;
    if (l == 0) sm[w] = v;
    __syncthreads();
    if (threadIdx.x == 0) {
        float s = 0.f;
#pragma unroll
        for (int k = 0; k < 8; k++) s += sm[k];
        atomicAdd(&d_gsum, s);
    }
}

// ---------------- final: gather + bias + attn scale + relu -------------------
__global__ __launch_bounds__(256) void finalize_kernel(
        const int* __restrict__ ci, const int* __restrict__ pi,
        const float* __restrict__ bfin, float* __restrict__ out, int E) {
    int e = blockIdx.x * 4 + (threadIdx.x >> 6);
    int lane = threadIdx.x & 63;
    if (e >= E) return;
    float a = d_expv[e] * (1.0f / d_gsum);
    int c = ci[e];
    int p = pi[e];
    const float4* gc = (const float4*)(d_g_cam + c * D);
    const float4* gp = (const float4*)(d_g_point + (size_t)p * D);
    const float4* b4 = (const float4*)bfin;
    float4 x = gc[lane], y = gp[lane], z = b4[lane];
    float4 r;
    r.x = fmaxf((x.x + y.x + z.x) * a, 0.f);
    r.y = fmaxf((x.y + y.y + z.y) * a, 0.f);
    r.z = fmaxf((x.z + y.z + z.z) * a, 0.f);
    r.w = fmaxf((x.w + y.w + z.w) * a, 0.f);
    ((float4*)out)[(size_t)e * 64 + lane] = r;
}

// ---------------- launch -----------------------------------------------------
extern "C" void kernel_launch(void* const* d_in, const int* in_sizes, int n_in,
                              void* d_out, int out_size) {
    const float* ef = (const float*)d_in[0];
    const int* ci = (const int*)d_in[1];
    const int* pi = (const int*)d_in[2];

    // skip scalar inputs (num_cams / num_points) if present
    int w = 3;
    while (w < n_in && in_sizes[w] <= 1) w++;
    const float* W_cam   = (const float*)d_in[w + 0];
    const float* W_point = (const float*)d_in[w + 1];
    const float* W_attn  = (const float*)d_in[w + 2];
    const float* W_final = (const float*)d_in[w + 3];
    const float* b_final = (const float*)d_in[w + 4];

    int E = in_sizes[1];
    float* out = (float*)d_out;

    void *pCamAgg, *pPointAgg;
    cudaGetSymbolAddress(&pCamAgg, d_cam_agg);
    cudaGetSymbolAddress(&pPointAgg, d_point_agg);

    cudaMemsetAsync(pCamAgg, 0, sizeof(float) * NUM_CAMS * D);
    cudaMemsetAsync(pPointAgg, 0, sizeof(float) * (size_t)NUM_POINTS * D);
    init_scalars_kernel<<<1, 1>>>();

    // Stage 1: precompute (257 blocks) + scatter, one launch
    stage1_kernel<<<257 + (E + 3) / 4, 256>>>(
        (const float4*)ef, ci, pi, W_cam, W_point, W_attn, W_final, E);

    // Stage 2: point GEMM + cam GEMM + both rowdots, one launch
    stage2_kernel<<<NPG + NCG + NRP + NRC, 256>>>();

    score_max_kernel<<<(E + 255) / 256, 256>>>(ci, pi, E);
    exp_sum_kernel<<<(E + 255) / 256, 256>>>(E);

    finalize_kernel<<<(E + 3) / 4, 256>>>(ci, pi, b_final, out, E);
}